// round 7
// baseline (speedup 1.0000x reference)
#include <cuda_runtime.h>

#define N_NODES 100000
#define N_EDGES 1600000
#define HMW 32            // concatenated mu(16) | logstd(16)
#define OUTC 16

// ---------------- scratch (device globals; no allocations allowed) -------------
__device__ int    g_is64;                  // edge_index dtype flag
__device__ int    g_degi[N_NODES];         // in-degree count (dst)
__device__ int    g_off [N_NODES];         // CSR exclusive offsets
__device__ int    g_cur [N_NODES];         // placement cursors
__device__ int    g_esrc[N_EDGES];         // CSR: src ids grouped by dst
__device__ float2 g_dxs [N_NODES];         // dis[n] * x[n]
__device__ float  g_gvec[N_NODES * HMW];   // g = dis * (h @ [Wmu|Wls])

__device__ __forceinline__ void load_edge(const void* ei, int e, int& src, int& dst) {
    if (g_is64) {
        const long long* p = (const long long*)ei;
        src = (int)p[e];
        dst = (int)p[N_EDGES + e];
    } else {
        const int* p = (const int*)ei;
        src = p[e];
        dst = p[N_EDGES + e];
    }
}

// ---------------- init: block 0 detects dtype; all blocks zero degree -----------
// int64 indices < 100000 have all-zero high words -> OR over 4096 words detects.
__global__ void k_init(const unsigned* ei_words) {
    if (blockIdx.x == 0) {
        __shared__ unsigned s_or[256];
        unsigned v = 0;
        for (int i = threadIdx.x; i < 4096; i += 256)
            v |= ei_words[2 * i + 1];
        s_or[threadIdx.x] = v;
        __syncthreads();
        for (int s = 128; s > 0; s >>= 1) {
            if (threadIdx.x < s) s_or[threadIdx.x] |= s_or[threadIdx.x + s];
            __syncthreads();
        }
        if (threadIdx.x == 0) g_is64 = (s_or[0] == 0u) ? 1 : 0;
    }
    int i = blockIdx.x * 256 + threadIdx.x;
    if (i < N_NODES / 4) ((int4*)g_degi)[i] = make_int4(0, 0, 0, 0);
}

// ---------------- degree (count of dst occurrences) -----------------------------
__global__ void k_deg(const void* ei) {
    int e = blockIdx.x * 256 + threadIdx.x;
    if (e >= N_EDGES) return;
    int dst;
    if (g_is64) dst = (int)((const long long*)ei)[N_EDGES + e];
    else        dst = ((const int*)ei)[N_EDGES + e];
    atomicAdd(&g_degi[dst], 1);
}

// ---------------- single-block exclusive scan: degi -> off, cur -----------------
#define SCAN_T 1024
#define SCAN_C 98          // 1024 * 98 = 100352 >= N_NODES
__global__ void __launch_bounds__(SCAN_T) k_scan() {
    __shared__ int ssum[SCAN_T];
    int t = threadIdx.x;
    int beg = t * SCAN_C;
    int s = 0;
    for (int i = 0; i < SCAN_C; i++) {
        int idx = beg + i;
        if (idx < N_NODES) s += g_degi[idx];
    }
    ssum[t] = s;
    __syncthreads();
    for (int d = 1; d < SCAN_T; d <<= 1) {   // Hillis-Steele inclusive scan
        int v = (t >= d) ? ssum[t - d] : 0;
        __syncthreads();
        ssum[t] += v;
        __syncthreads();
    }
    int run = (t > 0) ? ssum[t - 1] : 0;     // exclusive base for this chunk
    for (int i = 0; i < SCAN_C; i++) {
        int idx = beg + i;
        if (idx < N_NODES) {
            g_off[idx] = run;
            g_cur[idx] = run;
            run += g_degi[idx];
        }
    }
}

// ---------------- CSR placement + dxs precompute --------------------------------
__global__ void k_place(const void* ei, const float* __restrict__ x) {
    int tid = blockIdx.x * 256 + threadIdx.x;
    if (tid < N_NODES) {
        float d = rsqrtf(1.0f + (float)g_degi[tid]);
        float2 xv = ((const float2*)x)[tid];
        g_dxs[tid] = make_float2(d * xv.x, d * xv.y);
    }
    if (tid >= N_EDGES) return;
    int src, dst;
    load_edge(ei, tid, src, dst);
    int pos = atomicAdd(&g_cur[dst], 1);
    g_esrc[pos] = src;
}

// ---------------- fused layer-1 gather + dense ----------------------------------
// agg = sum over in-edges of dxs[src] (4-way edge-parallel per node, shfl-reduce)
// then h = relu(aggX @ W1 + b1); gvec = dis * (h @ [Wmu|Wls]).
// 4 threads/node (8 outputs each) x 4 nodes/thread; weights broadcast float4 LDS.
__global__ void __launch_bounds__(256) k_hidden(
        const float* __restrict__ x, const float* __restrict__ W1,
        const float* __restrict__ b1,
        const float* __restrict__ Wmu, const float* __restrict__ Wls) {
    __shared__ float4 sW4[64][8];   // [k][j/4] of concatenated [Wmu|Wls], 4KB
    __shared__ float4 sWb[64];      // (W1[0][k], W1[1][k], b1[k], 0)

    int t = threadIdx.x;
    for (int i = t; i < 512; i += 256) {
        int k = i >> 3, q = i & 7;
        sW4[k][q] = (q < 4) ? ((const float4*)Wmu)[k * 4 + q]
                            : ((const float4*)Wls)[k * 4 + (q - 4)];
    }
    if (t < 64) sWb[t] = make_float4(W1[t], W1[64 + t], b1[t], 0.0f);
    __syncthreads();

    int part = t & 3;               // which 8 of the 32 outputs / edge-lane
    int u    = t >> 2;              // 0..63
    int base = blockIdx.x * 256;

    float a0[4], a1[4], dd[4];
    #pragma unroll
    for (int i = 0; i < 4; i++) {
        int n = base + u + 64 * i;
        int nc = (n < N_NODES) ? n : 0;
        int off = g_off[nc], cnt = g_degi[nc];
        float sx = 0.0f, sy = 0.0f;
        for (int j = part; j < cnt; j += 4) {
            float2 v = g_dxs[g_esrc[off + j]];
            sx += v.x; sy += v.y;
        }
        sx += __shfl_xor_sync(0xFFFFFFFF, sx, 1);
        sy += __shfl_xor_sync(0xFFFFFFFF, sy, 1);
        sx += __shfl_xor_sync(0xFFFFFFFF, sx, 2);
        sy += __shfl_xor_sync(0xFFFFFFFF, sy, 2);
        float d = rsqrtf(1.0f + (float)cnt);
        float2 xv = ((const float2*)x)[nc];
        a0[i] = d * sx + d * d * xv.x;
        a1[i] = d * sy + d * d * xv.y;
        dd[i] = d;
    }

    float acc[4][8];
    #pragma unroll
    for (int i = 0; i < 4; i++)
        #pragma unroll
        for (int j = 0; j < 8; j++) acc[i][j] = 0.0f;

    int q0 = part * 2;
    #pragma unroll 4
    for (int k = 0; k < 64; k++) {
        float4 wb = sWb[k];
        float4 wA = sW4[k][q0];
        float4 wB = sW4[k][q0 + 1];
        #pragma unroll
        for (int i = 0; i < 4; i++) {
            float hk = fmaxf(0.0f, fmaf(a0[i], wb.x, fmaf(a1[i], wb.y, wb.z)));
            acc[i][0] = fmaf(hk, wA.x, acc[i][0]);
            acc[i][1] = fmaf(hk, wA.y, acc[i][1]);
            acc[i][2] = fmaf(hk, wA.z, acc[i][2]);
            acc[i][3] = fmaf(hk, wA.w, acc[i][3]);
            acc[i][4] = fmaf(hk, wB.x, acc[i][4]);
            acc[i][5] = fmaf(hk, wB.y, acc[i][5]);
            acc[i][6] = fmaf(hk, wB.z, acc[i][6]);
            acc[i][7] = fmaf(hk, wB.w, acc[i][7]);
        }
    }

    #pragma unroll
    for (int i = 0; i < 4; i++) {
        int n = base + u + 64 * i;
        if (n < N_NODES) {
            float4* gout = (float4*)(g_gvec + n * HMW + part * 8);
            gout[0] = make_float4(dd[i] * acc[i][0], dd[i] * acc[i][1],
                                  dd[i] * acc[i][2], dd[i] * acc[i][3]);
            gout[1] = make_float4(dd[i] * acc[i][4], dd[i] * acc[i][5],
                                  dd[i] * acc[i][6], dd[i] * acc[i][7]);
        }
    }
}

// ---------------- fused layer-2 gather + epilogue --------------------------------
// 8 lanes per node (feature-quad q each), 4 nodes per warp. Per edge: broadcast
// esrc load + 8 coalesced float4 gathers of gvec[src]; NO atomics. Then
// out = dis*(agg + gvec[n]) + bias, split mu / logstd.
__global__ void __launch_bounds__(256) k_gather2(
        const float* __restrict__ bmu, const float* __restrict__ bls,
        float* __restrict__ out) {
    int t = threadIdx.x;
    int lane = t & 31, w = t >> 5;
    int q = lane & 7, sub = lane >> 3;
    int n = blockIdx.x * 32 + w * 4 + sub;
    if (n >= N_NODES) return;

    int off = g_off[n], cnt = g_degi[n];
    const float4* gv4 = (const float4*)g_gvec;

    float4 accA = make_float4(0.f, 0.f, 0.f, 0.f);
    float4 accB = make_float4(0.f, 0.f, 0.f, 0.f);
    int e = 0;
    for (; e + 2 <= cnt; e += 2) {
        int s0 = g_esrc[off + e];
        int s1 = g_esrc[off + e + 1];
        float4 v0 = gv4[s0 * 8 + q];
        float4 v1 = gv4[s1 * 8 + q];
        accA.x += v0.x; accA.y += v0.y; accA.z += v0.z; accA.w += v0.w;
        accB.x += v1.x; accB.y += v1.y; accB.z += v1.z; accB.w += v1.w;
    }
    if (e < cnt) {
        float4 v = gv4[g_esrc[off + e] * 8 + q];
        accA.x += v.x; accA.y += v.y; accA.z += v.z; accA.w += v.w;
    }
    accA.x += accB.x; accA.y += accB.y; accA.z += accB.z; accA.w += accB.w;

    float4 g = gv4[n * 8 + q];
    float d = rsqrtf(1.0f + (float)cnt);
    float4 b = (q < 4) ? ((const float4*)bmu)[q] : ((const float4*)bls)[q - 4];
    float4 v = make_float4(fmaf(d, accA.x + g.x, b.x), fmaf(d, accA.y + g.y, b.y),
                           fmaf(d, accA.z + g.z, b.z), fmaf(d, accA.w + g.w, b.w));
    float* dst = (q < 4) ? out + n * OUTC + q * 4
                         : out + N_NODES * OUTC + n * OUTC + (q - 4) * 4;
    *(float4*)dst = v;
}

extern "C" void kernel_launch(void* const* d_in, const int* in_sizes, int n_in,
                              void* d_out, int out_size) {
    const float* x    = (const float*)d_in[0];
    const void*  ei   = d_in[1];                 // int32 or int64, detected on device
    const float* W1   = (const float*)d_in[2];
    const float* b1   = (const float*)d_in[3];
    const float* Wmu  = (const float*)d_in[4];
    const float* bmu  = (const float*)d_in[5];
    const float* Wls  = (const float*)d_in[6];
    const float* bls  = (const float*)d_in[7];
    float* out = (float*)d_out;

    const int IB  = (N_NODES / 4 + 255) / 256;            // 98
    const int EB  = (N_EDGES + 255) / 256;                // 6250
    const int HB  = (N_NODES + 255) / 256;                // 391
    const int GB  = (N_NODES + 31) / 32;                  // 3125

    k_init<<<IB, 256>>>((const unsigned*)ei);
    k_deg<<<EB, 256>>>(ei);
    k_scan<<<1, SCAN_T>>>();
    k_place<<<EB, 256>>>(ei, x);
    k_hidden<<<HB, 256>>>(x, W1, b1, Wmu, Wls);
    k_gather2<<<GB, 256>>>(bmu, bls, out);
}

// round 8
// speedup vs baseline: 2.4758x; 2.4758x over previous
#include <cuda_runtime.h>

#define N_NODES 100000
#define N_EDGES 1600000
#define HMW 32            // concatenated mu(16) | logstd(16)
#define OUTC 16

// ---------------- scratch (device globals; no allocations allowed) -------------
__device__ float g_deg  [N_NODES];         // in-degree count (dst)
__device__ float g_acc0 [N_NODES * 2];     // layer-1 aggregation of dis*x
__device__ float g_gvec [N_NODES * HMW];   // g = dis * (h @ [Wmu|Wls])
__device__ float g_acc1 [N_NODES * HMW];   // layer-2 accumulator (init = gvec)
__device__ int   g_src32[N_EDGES];         // compacted int32 src
__device__ int   g_dst32[N_EDGES];         // compacted int32 dst
__device__ int   g_is64;                   // edge_index dtype flag

// ---------------- vectorized L2 reductions (sm_90+) -----------------------------
__device__ __forceinline__ void red_add_v4(float* addr, float4 v) {
    asm volatile("red.global.add.v4.f32 [%0], {%1, %2, %3, %4};"
                 :: "l"(addr), "f"(v.x), "f"(v.y), "f"(v.z), "f"(v.w) : "memory");
}
__device__ __forceinline__ void red_add_v2(float* addr, float a, float b) {
    asm volatile("red.global.add.v2.f32 [%0], {%1, %2};"
                 :: "l"(addr), "f"(a), "f"(b) : "memory");
}

// ---------------- init: block 0 detects dtype; all blocks zero deg + acc0 -------
// int64 indices < 100000 have all-zero high words -> OR over 4096 words detects.
__global__ void k_init(const unsigned* ei_words) {
    if (blockIdx.x == 0) {
        __shared__ unsigned s_or[256];
        unsigned v = 0;
        for (int i = threadIdx.x; i < 4096; i += 256)
            v |= ei_words[2 * i + 1];
        s_or[threadIdx.x] = v;
        __syncthreads();
        for (int s = 128; s > 0; s >>= 1) {
            if (threadIdx.x < s) s_or[threadIdx.x] |= s_or[threadIdx.x + s];
            __syncthreads();
        }
        if (threadIdx.x == 0) g_is64 = (s_or[0] == 0u) ? 1 : 0;
    }
    const float4 z = make_float4(0.f, 0.f, 0.f, 0.f);
    int i = blockIdx.x * 256 + threadIdx.x;
    if (i < N_NODES * 2 / 4) ((float4*)g_acc0)[i] = z;   // 50000 float4
    if (i < N_NODES / 4)     ((float4*)g_deg )[i] = z;   // 25000 float4
}

// ---------------- degree + edge compaction to int32 -----------------------------
__global__ void k_deg(const void* ei) {
    int e = blockIdx.x * 256 + threadIdx.x;
    if (e >= N_EDGES) return;
    int src, dst;
    if (g_is64) {
        const long long* p = (const long long*)ei;
        src = (int)p[e];
        dst = (int)p[N_EDGES + e];
    } else {
        const int* p = (const int*)ei;
        src = p[e];
        dst = p[N_EDGES + e];
    }
    g_src32[e] = src;
    g_dst32[e] = dst;
    atomicAdd(&g_deg[dst], 1.0f);
}

// ---------------- layer-1 scatter: acc0[dst] += dis[src] * x[src]  (2 feats) ----
__global__ void k_scatter0(const float* __restrict__ x) {
    int e = blockIdx.x * 256 + threadIdx.x;
    if (e >= N_EDGES) return;
    int src = g_src32[e];
    int dst = g_dst32[e];
    float ds = rsqrtf(1.0f + g_deg[src]);
    float2 xv = ((const float2*)x)[src];
    red_add_v2(&g_acc0[2 * dst], ds * xv.x, ds * xv.y);
}

// ---------------- dense: h = relu(aggX @ W1 + b1); g = dis * (h @ [Wmu|Wls]) ----
// 4 threads/node (8 outputs each) x 4 nodes/thread, 128-thr blocks for better
// wave balance. Writes gvec AND seeds acc1 with the self-loop term (= gvec),
// eliminating the acc1 zeroing pass and k_out's gvec read.
__global__ void __launch_bounds__(128) k_hidden(
        const float* __restrict__ x, const float* __restrict__ W1,
        const float* __restrict__ b1,
        const float* __restrict__ Wmu, const float* __restrict__ Wls) {
    __shared__ float4 sW4[64][8];   // [k][j/4] of concatenated [Wmu|Wls], 4KB
    __shared__ float4 sWb[64];      // (W1[0][k], W1[1][k], b1[k], 0)

    int t = threadIdx.x;
    for (int i = t; i < 512; i += 128) {
        int k = i >> 3, q = i & 7;
        sW4[k][q] = (q < 4) ? ((const float4*)Wmu)[k * 4 + q]
                            : ((const float4*)Wls)[k * 4 + (q - 4)];
    }
    if (t < 64) sWb[t] = make_float4(W1[t], W1[64 + t], b1[t], 0.0f);
    __syncthreads();

    int part = t & 3;               // which 8 of the 32 outputs
    int u    = t >> 2;              // 0..31
    int base = blockIdx.x * 128;

    float a0[4], a1[4], dd[4];
    #pragma unroll
    for (int i = 0; i < 4; i++) {
        int n = base + u + 32 * i;
        int nc = (n < N_NODES) ? n : 0;
        float d = rsqrtf(1.0f + g_deg[nc]);
        float2 xv = ((const float2*)x)[nc];
        float2 av = ((const float2*)g_acc0)[nc];
        a0[i] = d * av.x + d * d * xv.x;
        a1[i] = d * av.y + d * d * xv.y;
        dd[i] = d;
    }

    float acc[4][8];
    #pragma unroll
    for (int i = 0; i < 4; i++)
        #pragma unroll
        for (int j = 0; j < 8; j++) acc[i][j] = 0.0f;

    int q0 = part * 2;
    #pragma unroll 4
    for (int k = 0; k < 64; k++) {
        float4 wb = sWb[k];
        float4 wA = sW4[k][q0];
        float4 wB = sW4[k][q0 + 1];
        #pragma unroll
        for (int i = 0; i < 4; i++) {
            float hk = fmaxf(0.0f, fmaf(a0[i], wb.x, fmaf(a1[i], wb.y, wb.z)));
            acc[i][0] = fmaf(hk, wA.x, acc[i][0]);
            acc[i][1] = fmaf(hk, wA.y, acc[i][1]);
            acc[i][2] = fmaf(hk, wA.z, acc[i][2]);
            acc[i][3] = fmaf(hk, wA.w, acc[i][3]);
            acc[i][4] = fmaf(hk, wB.x, acc[i][4]);
            acc[i][5] = fmaf(hk, wB.y, acc[i][5]);
            acc[i][6] = fmaf(hk, wB.z, acc[i][6]);
            acc[i][7] = fmaf(hk, wB.w, acc[i][7]);
        }
    }

    #pragma unroll
    for (int i = 0; i < 4; i++) {
        int n = base + u + 32 * i;
        if (n < N_NODES) {
            float4 vA = make_float4(dd[i] * acc[i][0], dd[i] * acc[i][1],
                                    dd[i] * acc[i][2], dd[i] * acc[i][3]);
            float4 vB = make_float4(dd[i] * acc[i][4], dd[i] * acc[i][5],
                                    dd[i] * acc[i][6], dd[i] * acc[i][7]);
            float4* gout = (float4*)(g_gvec + n * HMW + part * 8);
            float4* aout = (float4*)(g_acc1 + n * HMW + part * 8);
            gout[0] = vA; gout[1] = vB;
            aout[0] = vA; aout[1] = vB;     // self-loop seed (replaces zeroing)
        }
    }
}

// ---------------- layer-2 scatter: acc1[dst][:] += g[src][:]  (32 feats) --------
// 8 threads per edge; each does one float4 gather + one independent red.v4
__global__ void k_scatter1() {
    long long tid = (long long)blockIdx.x * 256 + threadIdx.x;
    if (tid >= (long long)N_EDGES * 8) return;
    int e = (int)(tid >> 3), q = (int)(tid & 7);
    int src = g_src32[e];
    int dst = g_dst32[e];
    float4 v = ((const float4*)g_gvec)[src * 8 + q];
    red_add_v4(&g_acc1[dst * HMW + q * 4], v);
}

// ---------------- epilogue: out = dis*acc1 + bias; split mu / logstd ------------
__global__ void k_out(const float* __restrict__ bmu, const float* __restrict__ bls,
                      float* __restrict__ out) {
    int tid = blockIdx.x * 256 + threadIdx.x;       // over N_NODES * 8 float4s
    if (tid >= N_NODES * 8) return;
    int n = tid >> 3, q = tid & 7;
    float d = rsqrtf(1.0f + g_deg[n]);
    float4 a = ((const float4*)g_acc1)[tid];
    float4 b = (q < 4) ? ((const float4*)bmu)[q] : ((const float4*)bls)[q - 4];
    float4 v = make_float4(fmaf(d, a.x, b.x), fmaf(d, a.y, b.y),
                           fmaf(d, a.z, b.z), fmaf(d, a.w, b.w));
    float* dst = (q < 4) ? out + n * OUTC + q * 4
                         : out + N_NODES * OUTC + n * OUTC + (q - 4) * 4;
    *(float4*)dst = v;
}

extern "C" void kernel_launch(void* const* d_in, const int* in_sizes, int n_in,
                              void* d_out, int out_size) {
    const float* x    = (const float*)d_in[0];
    const void*  ei   = d_in[1];                 // int32 or int64, detected on device
    const float* W1   = (const float*)d_in[2];
    const float* b1   = (const float*)d_in[3];
    const float* Wmu  = (const float*)d_in[4];
    const float* bmu  = (const float*)d_in[5];
    const float* Wls  = (const float*)d_in[6];
    const float* bls  = (const float*)d_in[7];
    float* out = (float*)d_out;

    const int IB  = (N_NODES * 2 / 4 + 255) / 256;        // 196
    const int EB  = (N_EDGES + 255) / 256;                // 6250
    const int HB  = (N_NODES + 127) / 128;                // 782
    const int OB  = (N_NODES * 8 + 255) / 256;            // 3125
    const int S1B = (int)(((long long)N_EDGES * 8 + 255) / 256);  // 50000

    k_init<<<IB, 256>>>((const unsigned*)ei);
    k_deg<<<EB, 256>>>(ei);
    k_scatter0<<<EB, 256>>>(x);
    k_hidden<<<HB, 128>>>(x, W1, b1, Wmu, Wls);
    k_scatter1<<<S1B, 256>>>();
    k_out<<<OB, 256>>>(bmu, bls, out);
}